// round 4
// baseline (speedup 1.0000x reference)
#include <cuda_runtime.h>
#include <cuda_fp16.h>
#include <cuda_bf16.h>
#include <cstdint>

#define N_NODES   100000
#define N_EDGES   1600000
#define IN_FEATS  64
#define OUT_FEATS 64
#define DIM       3
#define N_KERNELS 4
#define KH        (N_KERNELS * OUT_FEATS)   // 256

#define SCAN_BLOCK 512
#define NBLK_SCAN  ((N_NODES + SCAN_BLOCK - 1) / SCAN_BLOCK)   // 196

// ---- scratch (allocation-free rule: __device__ globals) ----
__device__ __half  g_h[(size_t)N_NODES * KH];     // node projections fp16 [v][k][ch] (51 MB)
__device__ int     g_count[N_NODES];              // in-degree histogram
__device__ int     g_offsets[N_NODES + 1];        // CSR offsets (by dst)
__device__ int     g_cursor[N_NODES];             // fill cursors
__device__ int     g_bsum[NBLK_SCAN];             // scan block sums
__device__ int     g_perm[N_EDGES];               // edge permutation, grouped by dst

// ---------------------------------------------------------------------------
// Histogram (with zero pass)
// ---------------------------------------------------------------------------
__global__ void zero_count_kernel() {
    int i = blockIdx.x * blockDim.x + threadIdx.x;
    if (i < N_NODES) g_count[i] = 0;
}

__global__ void hist_kernel(const int* __restrict__ dst) {
    int e = blockIdx.x * blockDim.x + threadIdx.x;
    if (e < N_EDGES) atomicAdd(&g_count[dst[e]], 1);
}

// ---------------------------------------------------------------------------
// Two-level exclusive scan: g_count -> g_offsets (+ cursor copy)
// ---------------------------------------------------------------------------
__global__ __launch_bounds__(SCAN_BLOCK) void scan1_kernel() {
    __shared__ int tmp[SCAN_BLOCK];
    int t = threadIdx.x;
    int i = blockIdx.x * SCAN_BLOCK + t;
    int x = (i < N_NODES) ? g_count[i] : 0;
    tmp[t] = x;
    __syncthreads();
#pragma unroll
    for (int off = 1; off < SCAN_BLOCK; off <<= 1) {
        int v = (t >= off) ? tmp[t - off] : 0;
        __syncthreads();
        tmp[t] += v;
        __syncthreads();
    }
    if (i < N_NODES) g_offsets[i] = tmp[t] - x;
    if (t == SCAN_BLOCK - 1) g_bsum[blockIdx.x] = tmp[t];
}

__global__ __launch_bounds__(256) void scan2_kernel() {
    __shared__ int tmp[256];
    int t = threadIdx.x;
    int x = (t < NBLK_SCAN) ? g_bsum[t] : 0;
    tmp[t] = x;
    __syncthreads();
#pragma unroll
    for (int off = 1; off < 256; off <<= 1) {
        int v = (t >= off) ? tmp[t - off] : 0;
        __syncthreads();
        tmp[t] += v;
        __syncthreads();
    }
    if (t < NBLK_SCAN) g_bsum[t] = tmp[t] - x;
}

__global__ __launch_bounds__(SCAN_BLOCK) void scan3_kernel() {
    int i = blockIdx.x * SCAN_BLOCK + threadIdx.x;
    if (i < N_NODES) {
        int v = g_offsets[i] + g_bsum[blockIdx.x];
        g_offsets[i] = v;
        g_cursor[i]  = v;
    }
    if (i == 0) g_offsets[N_NODES] = N_EDGES;
}

// ---------------------------------------------------------------------------
// Slim binning: only the edge permutation (4B random write per edge)
// ---------------------------------------------------------------------------
__global__ __launch_bounds__(256) void perm_kernel(const int* __restrict__ dst) {
    int e = blockIdx.x * blockDim.x + threadIdx.x;
    if (e >= N_EDGES) return;
    int d = __ldg(dst + e);
    int pos = atomicAdd(&g_cursor[d], 1);
    g_perm[pos] = e;
}

// ---------------------------------------------------------------------------
// Projection: h[v, k, ch] = sum_j feat[v,j] * W_fc[k*64+ch, j]  -> fp16
// ---------------------------------------------------------------------------
#define PROJ_TILE 32

__global__ __launch_bounds__(256) void proj_kernel(const float* __restrict__ feat,
                                                   const float* __restrict__ W_fc) {
    __shared__ float sf[PROJ_TILE][IN_FEATS];

    const int o = threadIdx.x;
    const int node0 = blockIdx.x * PROJ_TILE;

    float w[IN_FEATS];
    const float4* wp = reinterpret_cast<const float4*>(W_fc + (size_t)o * IN_FEATS);
#pragma unroll
    for (int q = 0; q < IN_FEATS / 4; q++) {
        float4 v = wp[q];
        w[4*q+0] = v.x; w[4*q+1] = v.y; w[4*q+2] = v.z; w[4*q+3] = v.w;
    }

    const float4* fp = reinterpret_cast<const float4*>(feat + (size_t)node0 * IN_FEATS);
#pragma unroll
    for (int q = 0; q < 2; q++) {
        int idx = threadIdx.x + q * 256;
        float4 v = fp[idx];
        int n = idx >> 4;
        int c = (idx & 15) * 4;
        sf[n][c+0] = v.x; sf[n][c+1] = v.y; sf[n][c+2] = v.z; sf[n][c+3] = v.w;
    }
    __syncthreads();

#pragma unroll 4
    for (int n = 0; n < PROJ_TILE; n++) {
        float acc = 0.f;
#pragma unroll
        for (int j = 0; j < IN_FEATS; j++)
            acc = fmaf(w[j], sf[n][j], acc);
        g_h[(size_t)(node0 + n) * KH + o] = __float2half_rn(acc);
    }
}

// ---------------------------------------------------------------------------
// Aggregation: one warp per dst node, no atomics.
// Lane owns channels 2*lane, 2*lane+1. Gaussian weights computed in-loop:
// lane (lane&3)==k evaluates exp for kernel k; shfl from lanes 0..3.
// out[v] = feat[v] + bias + sum_{edges->v} sum_k g_k * h[src, k, :]
// ---------------------------------------------------------------------------
#define AGG_WARPS 8

__global__ __launch_bounds__(AGG_WARPS * 32) void agg_kernel(const float* __restrict__ feat,
                                                             const float* __restrict__ bias,
                                                             const float* __restrict__ pseudo,
                                                             const int*   __restrict__ src,
                                                             const float* __restrict__ mu,
                                                             const float* __restrict__ inv_sigma,
                                                             float* __restrict__ out) {
    const int warp = threadIdx.x >> 5;
    const int lane = threadIdx.x & 31;
    const int v = blockIdx.x * AGG_WARPS + warp;
    if (v >= N_NODES) return;

    const int beg = g_offsets[v];
    const int end = g_offsets[v + 1];

    // hoist per-lane Gaussian params (kid = lane & 3)
    const int kid = lane & 3;
    const float m0 = __ldg(mu + kid*3 + 0);
    const float m1 = __ldg(mu + kid*3 + 1);
    const float m2 = __ldg(mu + kid*3 + 2);
    float s0 = __ldg(inv_sigma + kid*3 + 0);
    float s1 = __ldg(inv_sigma + kid*3 + 1);
    float s2 = __ldg(inv_sigma + kid*3 + 2);
    const float q0 = -0.5f * s0 * s0;
    const float q1 = -0.5f * s1 * s1;
    const float q2 = -0.5f * s2 * s2;

    float2 acc = *reinterpret_cast<const float2*>(feat + (size_t)v * OUT_FEATS + lane * 2);
    float2 b   = *reinterpret_cast<const float2*>(bias + lane * 2);
    acc.x += b.x; acc.y += b.y;

    const unsigned FULL = 0xffffffffu;

    int i = beg;
    for (; i + 2 <= end; i += 2) {
#pragma unroll
        for (int u = 0; u < 2; u++) {
            int e = __ldg(g_perm + i + u);
            int s = __ldg(src + e);
            float px = __ldg(pseudo + 3*e + 0);
            float py = __ldg(pseudo + 3*e + 1);
            float pz = __ldg(pseudo + 3*e + 2);
            float d0 = px - m0, d1 = py - m1, d2 = pz - m2;
            float gv = __expf(q0*d0*d0 + q1*d1*d1 + q2*d2*d2);
            float g0 = __shfl_sync(FULL, gv, 0);
            float g1 = __shfl_sync(FULL, gv, 1);
            float g2 = __shfl_sync(FULL, gv, 2);
            float g3 = __shfl_sync(FULL, gv, 3);
            const __half2* hp = reinterpret_cast<const __half2*>(g_h + (size_t)s * KH);
            float2 f0 = __half22float2(__ldg(hp + 0*32 + lane));
            float2 f1 = __half22float2(__ldg(hp + 1*32 + lane));
            float2 f2 = __half22float2(__ldg(hp + 2*32 + lane));
            float2 f3 = __half22float2(__ldg(hp + 3*32 + lane));
            acc.x += g0*f0.x + g1*f1.x + g2*f2.x + g3*f3.x;
            acc.y += g0*f0.y + g1*f1.y + g2*f2.y + g3*f3.y;
        }
    }
    for (; i < end; i++) {
        int e = __ldg(g_perm + i);
        int s = __ldg(src + e);
        float px = __ldg(pseudo + 3*e + 0);
        float py = __ldg(pseudo + 3*e + 1);
        float pz = __ldg(pseudo + 3*e + 2);
        float d0 = px - m0, d1 = py - m1, d2 = pz - m2;
        float gv = __expf(q0*d0*d0 + q1*d1*d1 + q2*d2*d2);
        float g0 = __shfl_sync(FULL, gv, 0);
        float g1 = __shfl_sync(FULL, gv, 1);
        float g2 = __shfl_sync(FULL, gv, 2);
        float g3 = __shfl_sync(FULL, gv, 3);
        const __half2* hp = reinterpret_cast<const __half2*>(g_h + (size_t)s * KH);
        float2 f0 = __half22float2(__ldg(hp + 0*32 + lane));
        float2 f1 = __half22float2(__ldg(hp + 1*32 + lane));
        float2 f2 = __half22float2(__ldg(hp + 2*32 + lane));
        float2 f3 = __half22float2(__ldg(hp + 3*32 + lane));
        acc.x += g0*f0.x + g1*f1.x + g2*f2.x + g3*f3.x;
        acc.y += g0*f0.y + g1*f1.y + g2*f2.y + g3*f3.y;
    }

    *reinterpret_cast<float2*>(out + (size_t)v * OUT_FEATS + lane * 2) = acc;
}

// ---------------------------------------------------------------------------
// Launch
// ---------------------------------------------------------------------------
extern "C" void kernel_launch(void* const* d_in, const int* in_sizes, int n_in,
                              void* d_out, int out_size) {
    const float* feat      = (const float*)d_in[0];   // [N, 64]
    const float* pseudo    = (const float*)d_in[1];   // [E, 3]
    const int*   src       = (const int*)  d_in[2];   // [E]
    const int*   dst       = (const int*)  d_in[3];   // [E]
    const float* W_fc      = (const float*)d_in[4];   // [256, 64]
    const float* mu        = (const float*)d_in[5];   // [4, 3]
    const float* inv_sigma = (const float*)d_in[6];   // [4, 3]
    const float* bias      = (const float*)d_in[7];   // [64]
    float* out = (float*)d_out;                       // [N, 64]

    // Node projections (fp16)
    proj_kernel<<<(N_NODES + PROJ_TILE - 1) / PROJ_TILE, 256>>>(feat, W_fc);

    // Slim CSR build (by dst): histogram -> scan -> permutation
    zero_count_kernel<<<(N_NODES + 255) / 256, 256>>>();
    hist_kernel<<<(N_EDGES + 255) / 256, 256>>>(dst);
    scan1_kernel<<<NBLK_SCAN, SCAN_BLOCK>>>();
    scan2_kernel<<<1, 256>>>();
    scan3_kernel<<<NBLK_SCAN, SCAN_BLOCK>>>();
    perm_kernel<<<(N_EDGES + 255) / 256, 256>>>(dst);

    // Atomic-free aggregation + residual + bias
    agg_kernel<<<(N_NODES + AGG_WARPS - 1) / AGG_WARPS, AGG_WARPS * 32>>>(
        feat, bias, pseudo, src, mu, inv_sigma, out);
}

// round 5
// speedup vs baseline: 1.1204x; 1.1204x over previous
#include <cuda_runtime.h>
#include <cuda_fp16.h>
#include <cuda_bf16.h>
#include <cstdint>

#define N_NODES   100000
#define N_EDGES   1600000
#define IN_FEATS  64
#define OUT_FEATS 64
#define DIM       3
#define N_KERNELS 4
#define KH        (N_KERNELS * OUT_FEATS)   // 256

#define SCAN_BLOCK 512
#define NBLK_SCAN  ((N_NODES + SCAN_BLOCK - 1) / SCAN_BLOCK)   // 196

// ---- scratch (allocation-free rule: __device__ globals) ----
__device__ __half  g_h[(size_t)N_NODES * KH];     // node projections fp16 (51 MB)
__device__ int     g_count[N_NODES];
__device__ int     g_offsets[N_NODES + 1];
__device__ int     g_cursor[N_NODES];
__device__ int     g_bsum[NBLK_SCAN];
__device__ float4  g_rec[N_EDGES];                // {src_bits, px, py, pz} grouped by dst

// ---------------------------------------------------------------------------
__global__ void zero_count_kernel() {
    int i = blockIdx.x * blockDim.x + threadIdx.x;
    if (i < N_NODES) g_count[i] = 0;
}

__global__ void hist_kernel(const int* __restrict__ dst) {
    int e = blockIdx.x * blockDim.x + threadIdx.x;
    if (e < N_EDGES) atomicAdd(&g_count[dst[e]], 1);
}

__global__ __launch_bounds__(SCAN_BLOCK) void scan1_kernel() {
    __shared__ int tmp[SCAN_BLOCK];
    int t = threadIdx.x;
    int i = blockIdx.x * SCAN_BLOCK + t;
    int x = (i < N_NODES) ? g_count[i] : 0;
    tmp[t] = x;
    __syncthreads();
#pragma unroll
    for (int off = 1; off < SCAN_BLOCK; off <<= 1) {
        int v = (t >= off) ? tmp[t - off] : 0;
        __syncthreads();
        tmp[t] += v;
        __syncthreads();
    }
    if (i < N_NODES) g_offsets[i] = tmp[t] - x;
    if (t == SCAN_BLOCK - 1) g_bsum[blockIdx.x] = tmp[t];
}

__global__ __launch_bounds__(256) void scan2_kernel() {
    __shared__ int tmp[256];
    int t = threadIdx.x;
    int x = (t < NBLK_SCAN) ? g_bsum[t] : 0;
    tmp[t] = x;
    __syncthreads();
#pragma unroll
    for (int off = 1; off < 256; off <<= 1) {
        int v = (t >= off) ? tmp[t - off] : 0;
        __syncthreads();
        tmp[t] += v;
        __syncthreads();
    }
    if (t < NBLK_SCAN) g_bsum[t] = tmp[t] - x;
}

__global__ __launch_bounds__(SCAN_BLOCK) void scan3_kernel() {
    int i = blockIdx.x * SCAN_BLOCK + threadIdx.x;
    if (i < N_NODES) {
        int v = g_offsets[i] + g_bsum[blockIdx.x];
        g_offsets[i] = v;
        g_cursor[i]  = v;
    }
    if (i == 0) g_offsets[N_NODES] = N_EDGES;
}

// ---------------------------------------------------------------------------
// Binning: pack {src, pseudo} into one float4 record at the dst-sorted slot
// ---------------------------------------------------------------------------
__global__ __launch_bounds__(256) void bin_kernel(const float* __restrict__ pseudo,
                                                  const int*   __restrict__ src,
                                                  const int*   __restrict__ dst) {
    int e = blockIdx.x * blockDim.x + threadIdx.x;
    if (e >= N_EDGES) return;
    float4 rec;
    rec.x = __int_as_float(__ldg(src + e));
    rec.y = __ldg(pseudo + 3*e + 0);
    rec.z = __ldg(pseudo + 3*e + 1);
    rec.w = __ldg(pseudo + 3*e + 2);
    int d = __ldg(dst + e);
    int pos = atomicAdd(&g_cursor[d], 1);
    g_rec[pos] = rec;
}

// ---------------------------------------------------------------------------
// Projection: h[v, k, ch] -> fp16
// ---------------------------------------------------------------------------
#define PROJ_TILE 32

__global__ __launch_bounds__(256) void proj_kernel(const float* __restrict__ feat,
                                                   const float* __restrict__ W_fc) {
    __shared__ float sf[PROJ_TILE][IN_FEATS];

    const int o = threadIdx.x;
    const int node0 = blockIdx.x * PROJ_TILE;

    float w[IN_FEATS];
    const float4* wp = reinterpret_cast<const float4*>(W_fc + (size_t)o * IN_FEATS);
#pragma unroll
    for (int q = 0; q < IN_FEATS / 4; q++) {
        float4 v = wp[q];
        w[4*q+0] = v.x; w[4*q+1] = v.y; w[4*q+2] = v.z; w[4*q+3] = v.w;
    }

    const float4* fp = reinterpret_cast<const float4*>(feat + (size_t)node0 * IN_FEATS);
#pragma unroll
    for (int q = 0; q < 2; q++) {
        int idx = threadIdx.x + q * 256;
        float4 v = fp[idx];
        int n = idx >> 4;
        int c = (idx & 15) * 4;
        sf[n][c+0] = v.x; sf[n][c+1] = v.y; sf[n][c+2] = v.z; sf[n][c+3] = v.w;
    }
    __syncthreads();

#pragma unroll 4
    for (int n = 0; n < PROJ_TILE; n++) {
        float acc = 0.f;
#pragma unroll
        for (int j = 0; j < IN_FEATS; j++)
            acc = fmaf(w[j], sf[n][j], acc);
        g_h[(size_t)(node0 + n) * KH + o] = __float2half_rn(acc);
    }
}

// ---------------------------------------------------------------------------
// Aggregation: warp per dst node, 4 edges per iteration, no atomics.
// Lane layout: group = lane>>3 (one edge each), sub = lane&7 (8 channels each).
// Gaussian: lane kid = lane&3 evaluates exp for kernel kid on its group's edge;
// broadcast via shfl from (lane&24)+k.
// ---------------------------------------------------------------------------
#define AGG_WARPS 8

__global__ __launch_bounds__(AGG_WARPS * 32) void agg_kernel(const float* __restrict__ feat,
                                                             const float* __restrict__ bias,
                                                             const float* __restrict__ mu,
                                                             const float* __restrict__ inv_sigma,
                                                             float* __restrict__ out) {
    const int warp = threadIdx.x >> 5;
    const int lane = threadIdx.x & 31;
    const int v = blockIdx.x * AGG_WARPS + warp;
    if (v >= N_NODES) return;

    const int beg = g_offsets[v];
    const int end = g_offsets[v + 1];

    const int group = lane >> 3;   // which edge in the 4-pack
    const int sub   = lane & 7;    // channel octet
    const int kid   = lane & 3;    // gaussian kernel this lane evaluates
    const int gbase = lane & 24;   // first lane of my group

    // per-lane Gaussian params
    const float m0 = __ldg(mu + kid*3 + 0);
    const float m1 = __ldg(mu + kid*3 + 1);
    const float m2 = __ldg(mu + kid*3 + 2);
    float s0 = __ldg(inv_sigma + kid*3 + 0);
    float s1 = __ldg(inv_sigma + kid*3 + 1);
    float s2 = __ldg(inv_sigma + kid*3 + 2);
    const float q0 = -0.5f * s0 * s0;
    const float q1 = -0.5f * s1 * s1;
    const float q2 = -0.5f * s2 * s2;

    const unsigned FULL = 0xffffffffu;

    float acc[8];
#pragma unroll
    for (int j = 0; j < 8; j++) acc[j] = 0.f;

    for (int i = beg; i < end; i += 4) {
        const int idx = i + group;
        const bool active = idx < end;

        float4 rec = make_float4(0.f, 0.f, 0.f, 0.f);
        if (active) rec = __ldg(g_rec + idx);
        const int s = __float_as_int(rec.x);

        float d0 = rec.y - m0, d1 = rec.z - m1, d2 = rec.w - m2;
        float gv = active ? __expf(q0*d0*d0 + q1*d1*d1 + q2*d2*d2) : 0.f;
        float g0 = __shfl_sync(FULL, gv, gbase + 0);
        float g1 = __shfl_sync(FULL, gv, gbase + 1);
        float g2 = __shfl_sync(FULL, gv, gbase + 2);
        float g3 = __shfl_sync(FULL, gv, gbase + 3);

        float4 r0 = make_float4(0.f,0.f,0.f,0.f);
        float4 r1 = r0, r2 = r0, r3 = r0;
        if (active) {
            const float4* hp = reinterpret_cast<const float4*>(g_h + (size_t)s * KH);
            r0 = __ldg(hp + 0*8 + sub);    // k=0 row: 8 halves
            r1 = __ldg(hp + 1*8 + sub);
            r2 = __ldg(hp + 2*8 + sub);
            r3 = __ldg(hp + 3*8 + sub);
        }
        const __half2* h0 = reinterpret_cast<const __half2*>(&r0);
        const __half2* h1 = reinterpret_cast<const __half2*>(&r1);
        const __half2* h2 = reinterpret_cast<const __half2*>(&r2);
        const __half2* h3 = reinterpret_cast<const __half2*>(&r3);
#pragma unroll
        for (int q = 0; q < 4; q++) {
            float2 a = __half22float2(h0[q]);
            float2 b = __half22float2(h1[q]);
            float2 c = __half22float2(h2[q]);
            float2 d = __half22float2(h3[q]);
            acc[2*q+0] += g0*a.x + g1*b.x + g2*c.x + g3*d.x;
            acc[2*q+1] += g0*a.y + g1*b.y + g2*c.y + g3*d.y;
        }
    }

    // reduce across the 4 groups (lanes l, l+8, l+16, l+24 share channel set)
#pragma unroll
    for (int j = 0; j < 8; j++) {
        acc[j] += __shfl_down_sync(FULL, acc[j], 16);
        acc[j] += __shfl_down_sync(FULL, acc[j], 8);
    }

    // lanes 0..7: write channels sub*8 .. sub*8+7 with residual + bias
    if (lane < 8) {
        const float4* fp = reinterpret_cast<const float4*>(feat + (size_t)v * OUT_FEATS + lane * 8);
        const float4* bp = reinterpret_cast<const float4*>(bias + lane * 8);
        float4 fa = __ldg(fp + 0), fb = __ldg(fp + 1);
        float4 ba = __ldg(bp + 0), bb = __ldg(bp + 1);
        float4 oa, ob;
        oa.x = fa.x + ba.x + acc[0];
        oa.y = fa.y + ba.y + acc[1];
        oa.z = fa.z + ba.z + acc[2];
        oa.w = fa.w + ba.w + acc[3];
        ob.x = fb.x + bb.x + acc[4];
        ob.y = fb.y + bb.y + acc[5];
        ob.z = fb.z + bb.z + acc[6];
        ob.w = fb.w + bb.w + acc[7];
        float4* op = reinterpret_cast<float4*>(out + (size_t)v * OUT_FEATS + lane * 8);
        op[0] = oa;
        op[1] = ob;
    }
}

// ---------------------------------------------------------------------------
// Launch
// ---------------------------------------------------------------------------
extern "C" void kernel_launch(void* const* d_in, const int* in_sizes, int n_in,
                              void* d_out, int out_size) {
    const float* feat      = (const float*)d_in[0];
    const float* pseudo    = (const float*)d_in[1];
    const int*   src       = (const int*)  d_in[2];
    const int*   dst       = (const int*)  d_in[3];
    const float* W_fc      = (const float*)d_in[4];
    const float* mu        = (const float*)d_in[5];
    const float* inv_sigma = (const float*)d_in[6];
    const float* bias      = (const float*)d_in[7];
    float* out = (float*)d_out;

    // Node projections (fp16)
    proj_kernel<<<(N_NODES + PROJ_TILE - 1) / PROJ_TILE, 256>>>(feat, W_fc);

    // Slim CSR build (by dst)
    zero_count_kernel<<<(N_NODES + 255) / 256, 256>>>();
    hist_kernel<<<(N_EDGES + 255) / 256, 256>>>(dst);
    scan1_kernel<<<NBLK_SCAN, SCAN_BLOCK>>>();
    scan2_kernel<<<1, 256>>>();
    scan3_kernel<<<NBLK_SCAN, SCAN_BLOCK>>>();

    // Pack records grouped by dst
    bin_kernel<<<(N_EDGES + 255) / 256, 256>>>(pseudo, src, dst);

    // Atomic-free aggregation + residual + bias
    agg_kernel<<<(N_NODES + AGG_WARPS - 1) / AGG_WARPS, AGG_WARPS * 32>>>(
        feat, bias, mu, inv_sigma, out);
}

// round 7
// speedup vs baseline: 1.2644x; 1.1286x over previous
#include <cuda_runtime.h>
#include <cuda_fp16.h>
#include <cuda_bf16.h>
#include <cstdint>

#define N_NODES   100000
#define N_EDGES   1600000
#define IN_FEATS  64
#define OUT_FEATS 64
#define DIM       3
#define N_KERNELS 4
#define KH        (N_KERNELS * OUT_FEATS)   // 256

// Scratch for node projections h[N, K*OUT] in fp16 (allocation-free rule)
__device__ __half g_h[(size_t)N_NODES * KH];

// ---------------------------------------------------------------------------
// Kernel 1: fused projection + output init.
//   h[v, o] = sum_j feat[v,j] * W_fc[o,j]   (fp16)
//   out[v, :] = feat[v, :] + bias
// ---------------------------------------------------------------------------
#define PROJ_TILE 32

__global__ __launch_bounds__(256) void proj_kernel(const float* __restrict__ feat,
                                                   const float* __restrict__ W_fc,
                                                   const float* __restrict__ bias,
                                                   float* __restrict__ out) {
    __shared__ float sf[PROJ_TILE][IN_FEATS];

    const int o = threadIdx.x;                 // 0..255 output channel
    const int node0 = blockIdx.x * PROJ_TILE;

    // W row into registers (16 x float4)
    float w[IN_FEATS];
    const float4* wp = reinterpret_cast<const float4*>(W_fc + (size_t)o * IN_FEATS);
#pragma unroll
    for (int q = 0; q < IN_FEATS / 4; q++) {
        float4 v = wp[q];
        w[4*q+0] = v.x; w[4*q+1] = v.y; w[4*q+2] = v.z; w[4*q+3] = v.w;
    }

    // Cooperative feat tile load + fused out = feat + bias
    const float4* fp = reinterpret_cast<const float4*>(feat + (size_t)node0 * IN_FEATS);
    float4* op = reinterpret_cast<float4*>(out + (size_t)node0 * IN_FEATS);
    const float4* bp = reinterpret_cast<const float4*>(bias);
#pragma unroll
    for (int q = 0; q < 2; q++) {
        int idx = threadIdx.x + q * 256;       // float4 index within tile
        float4 v = fp[idx];
        int n = idx >> 4;                       // 16 float4 per node row
        int c = (idx & 15) * 4;
        sf[n][c+0] = v.x; sf[n][c+1] = v.y; sf[n][c+2] = v.z; sf[n][c+3] = v.w;
        float4 b = __ldg(bp + (idx & 15));
        v.x += b.x; v.y += b.y; v.z += b.z; v.w += b.w;
        op[idx] = v;                            // out = feat + bias
    }
    __syncthreads();

#pragma unroll 4
    for (int n = 0; n < PROJ_TILE; n++) {
        float acc = 0.f;
#pragma unroll
        for (int j = 0; j < IN_FEATS; j++)
            acc = fmaf(w[j], sf[n][j], acc);
        g_h[(size_t)(node0 + n) * KH + o] = __float2half_rn(acc);
    }
}

// ---------------------------------------------------------------------------
// L2 residency via createpolicy + cache_hint (any-width legal form).
// ---------------------------------------------------------------------------
__device__ __forceinline__ uint64_t make_policy_evict_last() {
    uint64_t p;
    asm("createpolicy.fractional.L2::evict_last.b64 %0, 1.0;" : "=l"(p));
    return p;
}
__device__ __forceinline__ uint64_t make_policy_evict_first() {
    uint64_t p;
    asm("createpolicy.fractional.L2::evict_first.b64 %0, 1.0;" : "=l"(p));
    return p;
}
__device__ __forceinline__ float4 ldg_hint_v4(const float4* p, uint64_t pol) {
    float4 v;
    asm volatile("ld.global.nc.L2::cache_hint.v4.f32 {%0, %1, %2, %3}, [%4], %5;"
                 : "=f"(v.x), "=f"(v.y), "=f"(v.z), "=f"(v.w) : "l"(p), "l"(pol));
    return v;
}
__device__ __forceinline__ float ldg_hint_f32(const float* p, uint64_t pol) {
    float v;
    asm volatile("ld.global.nc.L2::cache_hint.f32 %0, [%1], %2;"
                 : "=f"(v) : "l"(p), "l"(pol));
    return v;
}
__device__ __forceinline__ int ldg_hint_s32(const int* p, uint64_t pol) {
    int v;
    asm volatile("ld.global.nc.L2::cache_hint.b32 %0, [%1], %2;"
                 : "=r"(v) : "l"(p), "l"(pol));
    return v;
}

// ---------------------------------------------------------------------------
// Kernel 2: edge scatter (R2 layout + residency hints).
// 8 threads per edge; thread handles 8 consecutive output channels.
// ---------------------------------------------------------------------------
__global__ __launch_bounds__(256) void edge_kernel(const float* __restrict__ pseudo,
                                                   const int*   __restrict__ src,
                                                   const int*   __restrict__ dst,
                                                   const float* __restrict__ mu,
                                                   const float* __restrict__ inv_sigma,
                                                   float* __restrict__ out) {
    const int gid = blockIdx.x * blockDim.x + threadIdx.x;
    const int e   = gid >> 3;                  // edge index
    if (e >= N_EDGES) return;

    const uint64_t pol_keep   = make_policy_evict_last();
    const uint64_t pol_stream = make_policy_evict_first();

    const int lane = threadIdx.x & 31;
    const int sub  = gid & 7;                  // 0..7 within edge group
    const int kid  = sub & 3;                  // Gaussian kernel this lane evaluates

    // --- Gaussian weight for kernel `kid` ---
    float px = ldg_hint_f32(pseudo + 3*e + 0, pol_stream);
    float py = ldg_hint_f32(pseudo + 3*e + 1, pol_stream);
    float pz = ldg_hint_f32(pseudo + 3*e + 2, pol_stream);

    float d0 = px - __ldg(mu + kid*3 + 0);
    float d1 = py - __ldg(mu + kid*3 + 1);
    float d2 = pz - __ldg(mu + kid*3 + 2);
    float s0 = __ldg(inv_sigma + kid*3 + 0);
    float s1 = __ldg(inv_sigma + kid*3 + 1);
    float s2 = __ldg(inv_sigma + kid*3 + 2);

    float acc = d0*d0*s0*s0 + d1*d1*s1*s1 + d2*d2*s2*s2;
    float gv  = __expf(-0.5f * acc);

    // Broadcast g[0..3] within the 8-lane group (group base = lane & 24)
    const unsigned FULL = 0xffffffffu;
    const int base = lane & 24;
    float g0 = __shfl_sync(FULL, gv, base + 0);
    float g1 = __shfl_sync(FULL, gv, base + 1);
    float g2 = __shfl_sync(FULL, gv, base + 2);
    float g3 = __shfl_sync(FULL, gv, base + 3);

    const int s = ldg_hint_s32(src + e, pol_stream);
    const int d = ldg_hint_s32(dst + e, pol_stream);

    // Gather h[src, k*64 + sub*8 .. +7] (8 halves = 16 B) for k = 0..3, keep in L2
    const float4* hp = reinterpret_cast<const float4*>(g_h + (size_t)s * KH);
    float4 r0 = ldg_hint_v4(hp + 0*8 + sub, pol_keep);
    float4 r1 = ldg_hint_v4(hp + 1*8 + sub, pol_keep);
    float4 r2 = ldg_hint_v4(hp + 2*8 + sub, pol_keep);
    float4 r3 = ldg_hint_v4(hp + 3*8 + sub, pol_keep);

    const __half2* h0 = reinterpret_cast<const __half2*>(&r0);
    const __half2* h1 = reinterpret_cast<const __half2*>(&r1);
    const __half2* h2 = reinterpret_cast<const __half2*>(&r2);
    const __half2* h3 = reinterpret_cast<const __half2*>(&r3);

    float m[8];
#pragma unroll
    for (int q = 0; q < 4; q++) {
        float2 a = __half22float2(h0[q]);
        float2 b = __half22float2(h1[q]);
        float2 c = __half22float2(h2[q]);
        float2 dd = __half22float2(h3[q]);
        m[2*q+0] = g0*a.x + g1*b.x + g2*c.x + g3*dd.x;
        m[2*q+1] = g0*a.y + g1*b.y + g2*c.y + g3*dd.y;
    }

    float* op = out + (size_t)d * OUT_FEATS + sub * 8;
    asm volatile("red.global.add.v4.f32 [%0], {%1, %2, %3, %4};"
                 :: "l"(op), "f"(m[0]), "f"(m[1]), "f"(m[2]), "f"(m[3])
                 : "memory");
    asm volatile("red.global.add.v4.f32 [%0], {%1, %2, %3, %4};"
                 :: "l"(op + 4), "f"(m[4]), "f"(m[5]), "f"(m[6]), "f"(m[7])
                 : "memory");
}

// ---------------------------------------------------------------------------
// Launch: exactly 2 kernels per call (ncu's captured launch = edge_kernel)
// ---------------------------------------------------------------------------
extern "C" void kernel_launch(void* const* d_in, const int* in_sizes, int n_in,
                              void* d_out, int out_size) {
    const float* feat      = (const float*)d_in[0];   // [N, 64]
    const float* pseudo    = (const float*)d_in[1];   // [E, 3]
    const int*   src       = (const int*)  d_in[2];   // [E]
    const int*   dst       = (const int*)  d_in[3];   // [E]
    const float* W_fc      = (const float*)d_in[4];   // [256, 64]
    const float* mu        = (const float*)d_in[5];   // [4, 3]
    const float* inv_sigma = (const float*)d_in[6];   // [4, 3]
    const float* bias      = (const float*)d_in[7];   // [64]
    float* out = (float*)d_out;                       // [N, 64]

    // 1) h = feat @ W_fc^T (fp16) AND out = feat + bias (fused)
    proj_kernel<<<(N_NODES + PROJ_TILE - 1) / PROJ_TILE, 256>>>(feat, W_fc, bias, out);

    // 2) edge scatter with vector atomics
    {
        long long threads = (long long)N_EDGES * 8;
        int blocks = (int)((threads + 255) / 256);            // 50000
        edge_kernel<<<blocks, 256>>>(pseudo, src, dst, mu, inv_sigma, out);
    }
}

// round 8
// speedup vs baseline: 1.6238x; 1.2842x over previous
#include <cuda_runtime.h>
#include <cuda_fp16.h>
#include <cuda_bf16.h>
#include <mma.h>
#include <cstdint>

using namespace nvcuda;

#define N_NODES   100000
#define N_EDGES   1600000
#define IN_FEATS  64
#define OUT_FEATS 64
#define DIM       3
#define N_KERNELS 4
#define KH        (N_KERNELS * OUT_FEATS)   // 256

// ---- scratch (allocation-free rule) ----
__device__ __half g_h[(size_t)N_NODES * KH];   // node projections fp16 (51 MB)
__device__ __half g_W16[KH * IN_FEATS];        // W_fc in fp16 (32 KB)

// ---------------------------------------------------------------------------
// Kernel 0: convert W_fc to fp16 (one-time tiny kernel)
// ---------------------------------------------------------------------------
__global__ void wconv_kernel(const float* __restrict__ W_fc) {
    int i = blockIdx.x * blockDim.x + threadIdx.x;       // half2 index
    if (i < KH * IN_FEATS / 2) {
        float2 v = reinterpret_cast<const float2*>(W_fc)[i];
        reinterpret_cast<__half2*>(g_W16)[i] = __floats2half2_rn(v.x, v.y);
    }
}

// ---------------------------------------------------------------------------
// Kernel 1: tensor-core projection + fused out = feat + bias.
//   h[v, o] = sum_j feat[v,j] * W_fc[o,j]  (fp16 in, fp32 acc, fp16 out)
// Block: 256 threads (8 warps), 64 nodes. M-tiles=4, N-tiles=16 (of 16).
// Warp w owns n-tiles {2w, 2w+1}; loops over all 4 m-tiles.
// A: smem fp16 (converted feat tile). B: g_W16 global, col-major (L1-resident).
// ---------------------------------------------------------------------------
#define NT 64   // nodes per block

__global__ __launch_bounds__(256) void proj_mma_kernel(const float* __restrict__ feat,
                                                       const float* __restrict__ bias,
                                                       float* __restrict__ out) {
    __shared__ __half As[NT * IN_FEATS];     // 8 KB, row-major ld=64
    __shared__ float  stage[8][256];         // 8 KB, per-warp 16x16 C staging

    const int tid  = threadIdx.x;
    const int warp = tid >> 5;
    const int lane = tid & 31;
    const int node0 = blockIdx.x * NT;

    // --- load feat tile (fp32), convert to fp16 smem, fused out = feat + bias ---
    const float4* fsrc = reinterpret_cast<const float4*>(feat + (size_t)node0 * IN_FEATS);
    float4*       odst = reinterpret_cast<float4*>(out + (size_t)node0 * IN_FEATS);
    const float4* bp   = reinterpret_cast<const float4*>(bias);
    const int lim4 = min(NT, N_NODES - node0) * (IN_FEATS / 4);   // valid float4 count
#pragma unroll
    for (int q = 0; q < 4; q++) {
        int i = tid + q * 256;               // float4 index in tile (0..1023)
        float4 v = (i < lim4) ? fsrc[i] : make_float4(0.f, 0.f, 0.f, 0.f);
        __half2* adst = reinterpret_cast<__half2*>(As + i * 4);
        adst[0] = __floats2half2_rn(v.x, v.y);
        adst[1] = __floats2half2_rn(v.z, v.w);
        if (i < lim4) {
            float4 b = __ldg(bp + (i & 15));
            v.x += b.x; v.y += b.y; v.z += b.z; v.w += b.w;
            odst[i] = v;                     // out = feat + bias
        }
    }
    __syncthreads();

    // --- wmma: each warp: 2 n-tiles x 4 m-tiles, K = 4 steps of 16 ---
#pragma unroll
    for (int t = 0; t < 2; t++) {
        const int ni = warp * 2 + t;

        wmma::fragment<wmma::matrix_b, 16, 16, 16, __half, wmma::col_major> b[4];
#pragma unroll
        for (int k = 0; k < 4; k++)
            wmma::load_matrix_sync(b[k], g_W16 + (ni * 16) * IN_FEATS + k * 16, IN_FEATS);

#pragma unroll
        for (int mi = 0; mi < 4; mi++) {
            wmma::fragment<wmma::matrix_a, 16, 16, 16, __half, wmma::row_major> a;
            wmma::fragment<wmma::accumulator, 16, 16, 16, float> c;
            wmma::fill_fragment(c, 0.f);
#pragma unroll
            for (int k = 0; k < 4; k++) {
                wmma::load_matrix_sync(a, As + (mi * 16) * IN_FEATS + k * 16, IN_FEATS);
                wmma::mma_sync(c, a, b[k], c);
            }
            wmma::store_matrix_sync(stage[warp], c, 16, wmma::mem_row_major);
            __syncwarp();
            // lane -> (row = lane>>1, half-row = lane&1): 8 floats -> 8 halves -> 16B store
            const int row  = lane >> 1;
            const int hsel = lane & 1;
            const int node = node0 + mi * 16 + row;
            if (node < N_NODES) {
                const float* sp = stage[warp] + row * 16 + hsel * 8;
                __half2 h4[4];
#pragma unroll
                for (int q = 0; q < 4; q++)
                    h4[q] = __floats2half2_rn(sp[2*q], sp[2*q+1]);
                *reinterpret_cast<uint4*>(g_h + (size_t)node * KH + ni * 16 + hsel * 8) =
                    *reinterpret_cast<uint4*>(h4);
            }
            __syncwarp();
        }
    }
}

// ---------------------------------------------------------------------------
// L2 residency via createpolicy + cache_hint.
// ---------------------------------------------------------------------------
__device__ __forceinline__ uint64_t make_policy_evict_last() {
    uint64_t p;
    asm("createpolicy.fractional.L2::evict_last.b64 %0, 1.0;" : "=l"(p));
    return p;
}
__device__ __forceinline__ uint64_t make_policy_evict_first() {
    uint64_t p;
    asm("createpolicy.fractional.L2::evict_first.b64 %0, 1.0;" : "=l"(p));
    return p;
}
__device__ __forceinline__ float4 ldg_hint_v4(const float4* p, uint64_t pol) {
    float4 v;
    asm volatile("ld.global.nc.L2::cache_hint.v4.f32 {%0, %1, %2, %3}, [%4], %5;"
                 : "=f"(v.x), "=f"(v.y), "=f"(v.z), "=f"(v.w) : "l"(p), "l"(pol));
    return v;
}
__device__ __forceinline__ float ldg_hint_f32(const float* p, uint64_t pol) {
    float v;
    asm volatile("ld.global.nc.L2::cache_hint.f32 %0, [%1], %2;"
                 : "=f"(v) : "l"(p), "l"(pol));
    return v;
}
__device__ __forceinline__ int ldg_hint_s32(const int* p, uint64_t pol) {
    int v;
    asm volatile("ld.global.nc.L2::cache_hint.b32 %0, [%1], %2;"
                 : "=r"(v) : "l"(p), "l"(pol));
    return v;
}

// ---------------------------------------------------------------------------
// Kernel 2: edge scatter (unchanged from R7: 139 us).
// 8 threads per edge; thread handles 8 consecutive output channels.
// ---------------------------------------------------------------------------
__global__ __launch_bounds__(256) void edge_kernel(const float* __restrict__ pseudo,
                                                   const int*   __restrict__ src,
                                                   const int*   __restrict__ dst,
                                                   const float* __restrict__ mu,
                                                   const float* __restrict__ inv_sigma,
                                                   float* __restrict__ out) {
    const int gid = blockIdx.x * blockDim.x + threadIdx.x;
    const int e   = gid >> 3;                  // edge index
    if (e >= N_EDGES) return;

    const uint64_t pol_keep   = make_policy_evict_last();
    const uint64_t pol_stream = make_policy_evict_first();

    const int lane = threadIdx.x & 31;
    const int sub  = gid & 7;
    const int kid  = sub & 3;

    float px = ldg_hint_f32(pseudo + 3*e + 0, pol_stream);
    float py = ldg_hint_f32(pseudo + 3*e + 1, pol_stream);
    float pz = ldg_hint_f32(pseudo + 3*e + 2, pol_stream);

    float d0 = px - __ldg(mu + kid*3 + 0);
    float d1 = py - __ldg(mu + kid*3 + 1);
    float d2 = pz - __ldg(mu + kid*3 + 2);
    float s0 = __ldg(inv_sigma + kid*3 + 0);
    float s1 = __ldg(inv_sigma + kid*3 + 1);
    float s2 = __ldg(inv_sigma + kid*3 + 2);

    float acc = d0*d0*s0*s0 + d1*d1*s1*s1 + d2*d2*s2*s2;
    float gv  = __expf(-0.5f * acc);

    const unsigned FULL = 0xffffffffu;
    const int base = lane & 24;
    float g0 = __shfl_sync(FULL, gv, base + 0);
    float g1 = __shfl_sync(FULL, gv, base + 1);
    float g2 = __shfl_sync(FULL, gv, base + 2);
    float g3 = __shfl_sync(FULL, gv, base + 3);

    const int s = ldg_hint_s32(src + e, pol_stream);
    const int d = ldg_hint_s32(dst + e, pol_stream);

    const float4* hp = reinterpret_cast<const float4*>(g_h + (size_t)s * KH);
    float4 r0 = ldg_hint_v4(hp + 0*8 + sub, pol_keep);
    float4 r1 = ldg_hint_v4(hp + 1*8 + sub, pol_keep);
    float4 r2 = ldg_hint_v4(hp + 2*8 + sub, pol_keep);
    float4 r3 = ldg_hint_v4(hp + 3*8 + sub, pol_keep);

    const __half2* h0 = reinterpret_cast<const __half2*>(&r0);
    const __half2* h1 = reinterpret_cast<const __half2*>(&r1);
    const __half2* h2 = reinterpret_cast<const __half2*>(&r2);
    const __half2* h3 = reinterpret_cast<const __half2*>(&r3);

    float m[8];
#pragma unroll
    for (int q = 0; q < 4; q++) {
        float2 a = __half22float2(h0[q]);
        float2 b = __half22float2(h1[q]);
        float2 c = __half22float2(h2[q]);
        float2 dd = __half22float2(h3[q]);
        m[2*q+0] = g0*a.x + g1*b.x + g2*c.x + g3*dd.x;
        m[2*q+1] = g0*a.y + g1*b.y + g2*c.y + g3*dd.y;
    }

    float* op = out + (size_t)d * OUT_FEATS + sub * 8;
    asm volatile("red.global.add.v4.f32 [%0], {%1, %2, %3, %4};"
                 :: "l"(op), "f"(m[0]), "f"(m[1]), "f"(m[2]), "f"(m[3])
                 : "memory");
    asm volatile("red.global.add.v4.f32 [%0], {%1, %2, %3, %4};"
                 :: "l"(op + 4), "f"(m[4]), "f"(m[5]), "f"(m[6]), "f"(m[7])
                 : "memory");
}

// ---------------------------------------------------------------------------
// Launch
// ---------------------------------------------------------------------------
extern "C" void kernel_launch(void* const* d_in, const int* in_sizes, int n_in,
                              void* d_out, int out_size) {
    const float* feat      = (const float*)d_in[0];   // [N, 64]
    const float* pseudo    = (const float*)d_in[1];   // [E, 3]
    const int*   src       = (const int*)  d_in[2];   // [E]
    const int*   dst       = (const int*)  d_in[3];   // [E]
    const float* W_fc      = (const float*)d_in[4];   // [256, 64]
    const float* mu        = (const float*)d_in[5];   // [4, 3]
    const float* inv_sigma = (const float*)d_in[6];   // [4, 3]
    const float* bias      = (const float*)d_in[7];   // [64]
    float* out = (float*)d_out;                       // [N, 64]

    // 0) W -> fp16
    wconv_kernel<<<(KH * IN_FEATS / 2 + 255) / 256, 256>>>(W_fc);

    // 1) tensor-core projection + out = feat + bias
    proj_mma_kernel<<<(N_NODES + NT - 1) / NT, 256>>>(feat, bias, out);

    // 2) edge scatter with vector atomics
    {
        long long threads = (long long)N_EDGES * 8;
        int blocks = (int)((threads + 255) / 256);            // 50000
        edge_kernel<<<blocks, 256>>>(pseudo, src, dst, mu, inv_sigma, out);
    }
}